// round 2
// baseline (speedup 1.0000x reference)
#include <cuda_runtime.h>
#include <cstdint>
#include <math.h>

#define EMBED    64
#define BATCHSZ  131072
#define SEQLEN   5
#define TILE     64
#define NTILES   (BATCHSZ / TILE)
#define THREADS  256
#define XS       68   // slot row stride in floats (conflict-free LDS)

typedef unsigned long long ull;

// ---------------- smem layout (float offsets) ----------------
// weights
#define O_NW1 0
#define O_NB1 4096
#define O_NW2 4160
#define O_NB2 8256
#define O_AW1 8320
#define O_AB1 16512
#define O_AW2 16576
#define O_AB2 20672
#define O_OW1 20736
#define O_OB1 28928
#define O_OW2 28992
#define O_OB2 33088
#define O_TV  33152
// activation slots (64 rows x stride 68)
#define O_S0  33216
#define O_S1  (O_S0 + 64*XS)
#define O_S2  (O_S1 + 64*XS)
#define O_S3  (O_S2 + 64*XS)
#define O_H   (O_S3 + 64*XS)
#define SMEM_FLOATS (O_H + 64*XS)
#define SMEM_BYTES  (SMEM_FLOATS * 4)   // 219904 B

__device__ __forceinline__ ull pack2(float x) {
    ull p;
    asm("mov.b64 %0, {%1, %1};" : "=l"(p) : "f"(x));
    return p;
}
__device__ __forceinline__ void fma2(ull& d, ull a, ull b) {
    asm("fma.rn.f32x2 %0, %1, %2, %0;" : "+l"(d) : "l"(a), "l"(b));
}
__device__ __forceinline__ float2 unpack2(ull p) {
    float lo, hi;
    asm("mov.b64 {%0, %1}, %2;" : "=f"(lo), "=f"(hi) : "l"(p));
    return make_float2(lo, hi);
}

// GEMM: Y[64 x 64] = act( [X1 | X2] @ W + b ), all operands in smem.
// X1/X2: row bases, stride XS. X2 == nullptr => K = 64.
// W: [K][64] row-major. Y: stride XS.
__device__ __forceinline__ void mlp_gemm(
    const float* __restrict__ X1, const float* __restrict__ X2,
    const float* __restrict__ W, const float* __restrict__ B,
    float* __restrict__ Y, bool lrelu, int tid)
{
    const int rp = tid >> 3;          // 0..31 -> row pair
    const int cg = tid & 7;           // 0..7  -> 8-col group
    const int r0 = rp * 2;
    const int c0 = cg * 8;

    ull acc0[4], acc1[4];
    const ull* bp = (const ull*)(B + c0);
#pragma unroll
    for (int j = 0; j < 4; j++) { acc0[j] = bp[j]; acc1[j] = bp[j]; }

    const int nhalf = (X2 == nullptr) ? 1 : 2;
#pragma unroll 1
    for (int h = 0; h < nhalf; h++) {
        const float* xb = (h == 0) ? X1 : X2;
        const float* Wh = W + h * 64 * 64;
#pragma unroll 2
        for (int k = 0; k < 64; k += 4) {
            float4 xa4 = *(const float4*)(xb + r0 * XS + k);
            float4 xc4 = *(const float4*)(xb + (r0 + 1) * XS + k);
            float xa_s[4] = {xa4.x, xa4.y, xa4.z, xa4.w};
            float xc_s[4] = {xc4.x, xc4.y, xc4.z, xc4.w};
            const float* wk = Wh + k * 64 + c0;
#pragma unroll
            for (int kk = 0; kk < 4; kk++) {
                ulonglong2 w01 = *(const ulonglong2*)(wk + kk * 64);
                ulonglong2 w23 = *(const ulonglong2*)(wk + kk * 64 + 4);
                ull xap = pack2(xa_s[kk]);
                ull xcp = pack2(xc_s[kk]);
                fma2(acc0[0], xap, w01.x);
                fma2(acc0[1], xap, w01.y);
                fma2(acc0[2], xap, w23.x);
                fma2(acc0[3], xap, w23.y);
                fma2(acc1[0], xcp, w01.x);
                fma2(acc1[1], xcp, w01.y);
                fma2(acc1[2], xcp, w23.x);
                fma2(acc1[3], xcp, w23.y);
            }
        }
    }

#pragma unroll
    for (int rr = 0; rr < 2; rr++) {
        ull* a = rr ? acc1 : acc0;
        float* yrow = Y + (r0 + rr) * XS + c0;
#pragma unroll
        for (int j = 0; j < 4; j++) {
            float2 v = unpack2(a[j]);
            if (lrelu) {
                v.x = (v.x > 0.f) ? v.x : 0.01f * v.x;
                v.y = (v.y > 0.f) ? v.y : 0.01f * v.y;
            }
            *(float2*)(yrow + 2 * j) = v;
        }
    }
}

// Gather one embedding row (64 floats) into an smem slot row. 4 threads/row.
__device__ __forceinline__ void gather_row(const float* __restrict__ embed,
                                           int item, float* __restrict__ dstrow, int q)
{
    const float4* s = (const float4*)(embed + (size_t)item * EMBED);
    float4* d = (float4*)dstrow;
#pragma unroll
    for (int j = 0; j < 4; j++) d[q + 4 * j] = s[q + 4 * j];
}

// cosine * 10 reduce over 64 cols; 4 lanes per row.
__device__ __forceinline__ void reduce_rows(const float* __restrict__ Y,
                                            const float* __restrict__ tv,
                                            float tvnorm, float* __restrict__ out,
                                            int base, int tid)
{
    const int r = tid >> 2, q = tid & 3;
    const float4* er = (const float4*)(Y + r * XS + q * 16);
    const float4* tr = (const float4*)(tv + q * 16);
    float num = 0.f, ss = 0.f;
#pragma unroll
    for (int j = 0; j < 4; j++) {
        float4 e = er[j], t = tr[j];
        num += e.x * t.x + e.y * t.y + e.z * t.z + e.w * t.w;
        ss  += e.x * e.x + e.y * e.y + e.z * e.z + e.w * e.w;
    }
    num += __shfl_xor_sync(0xffffffffu, num, 1);
    ss  += __shfl_xor_sync(0xffffffffu, ss, 1);
    num += __shfl_xor_sync(0xffffffffu, num, 2);
    ss  += __shfl_xor_sync(0xffffffffu, ss, 2);
    if (q == 0) {
        float denom = fmaxf(sqrtf(ss), 1e-8f) * tvnorm;
        out[base + r] = num / denom * 10.0f;
    }
}

__device__ __forceinline__ void copy_w(float* __restrict__ dst,
                                       const float* __restrict__ src, int n, int tid)
{
    for (int i = tid * 4; i < n; i += THREADS * 4)
        *(float4*)(dst + i) = *(const float4*)(src + i);
}

__global__ __launch_bounds__(THREADS, 1)
void logicnet_kernel(const int* __restrict__ seq,
                     const int* __restrict__ pos_t,
                     const int* __restrict__ neg_t,
                     const float* __restrict__ embed,
                     const float* __restrict__ true_vec,
                     const float* __restrict__ nW1, const float* __restrict__ nb1,
                     const float* __restrict__ nW2, const float* __restrict__ nb2,
                     const float* __restrict__ aW1, const float* __restrict__ ab1,
                     const float* __restrict__ aW2, const float* __restrict__ ab2,
                     const float* __restrict__ oW1, const float* __restrict__ ob1,
                     const float* __restrict__ oW2, const float* __restrict__ ob2,
                     float* __restrict__ out)
{
    extern __shared__ float smem[];
    const int tid = threadIdx.x;

    // ---- load all weights + true_vec into smem (once per CTA) ----
    copy_w(smem + O_NW1, nW1, 4096, tid);
    copy_w(smem + O_NB1, nb1,   64, tid);
    copy_w(smem + O_NW2, nW2, 4096, tid);
    copy_w(smem + O_NB2, nb2,   64, tid);
    copy_w(smem + O_AW1, aW1, 8192, tid);
    copy_w(smem + O_AB1, ab1,   64, tid);
    copy_w(smem + O_AW2, aW2, 4096, tid);
    copy_w(smem + O_AB2, ab2,   64, tid);
    copy_w(smem + O_OW1, oW1, 8192, tid);
    copy_w(smem + O_OB1, ob1,   64, tid);
    copy_w(smem + O_OW2, oW2, 4096, tid);
    copy_w(smem + O_OB2, ob2,   64, tid);
    copy_w(smem + O_TV,  true_vec, 64, tid);
    __syncthreads();

    const float* s_nW1 = smem + O_NW1; const float* s_nb1 = smem + O_NB1;
    const float* s_nW2 = smem + O_NW2; const float* s_nb2 = smem + O_NB2;
    const float* s_aW1 = smem + O_AW1; const float* s_ab1 = smem + O_AB1;
    const float* s_aW2 = smem + O_AW2; const float* s_ab2 = smem + O_AB2;
    const float* s_oW1 = smem + O_OW1; const float* s_ob1 = smem + O_OB1;
    const float* s_oW2 = smem + O_OW2; const float* s_ob2 = smem + O_OB2;
    const float* s_tv  = smem + O_TV;
    float* S0 = smem + O_S0;
    float* S1 = smem + O_S1;
    float* S2 = smem + O_S2;
    float* S3 = smem + O_S3;
    float* H  = smem + O_H;

    // ||true_vec|| (each thread computes it once; constant across tiles)
    float tvss = 0.f;
#pragma unroll
    for (int c = 0; c < 64; c++) tvss += s_tv[c] * s_tv[c];
    const float tvnorm = fmaxf(sqrtf(tvss), 1e-8f);

    const int gr = tid >> 2, gq = tid & 3;   // gather/reduce mapping: 4 lanes per row

    for (int tile = blockIdx.x; tile < NTILES; tile += gridDim.x) {
        const int grow = tile * TILE + gr;

        // phase 1: gather e1->S0, e0->S1, e2->S2, e3->S3
        gather_row(embed, seq[grow * SEQLEN + 1], S0 + gr * XS, gq);
        gather_row(embed, seq[grow * SEQLEN + 0], S1 + gr * XS, gq);
        gather_row(embed, seq[grow * SEQLEN + 2], S2 + gr * XS, gq);
        gather_row(embed, seq[grow * SEQLEN + 3], S3 + gr * XS, gq);
        __syncthreads();

        // n1 = NOT(e1): S0 -> H -> S0
        mlp_gemm(S0, nullptr, s_nW1, s_nb1, H, true, tid);  __syncthreads();
        mlp_gemm(H,  nullptr, s_nW2, s_nb2, S0, false, tid); __syncthreads();
        // I5 = AND(e0, n1): (S1,S0) -> H -> S1
        mlp_gemm(S1, S0, s_aW1, s_ab1, H, true, tid);  __syncthreads();
        mlp_gemm(H, nullptr, s_aW2, s_ab2, S1, false, tid); __syncthreads();
        // I6 = OR(e2, e3): (S2,S3) -> H -> S2
        mlp_gemm(S2, S3, s_oW1, s_ob1, H, true, tid);  __syncthreads();
        mlp_gemm(H, nullptr, s_oW2, s_ob2, S2, false, tid); __syncthreads();
        // I7 = AND(I5, I6): (S1,S2) -> H -> S1
        mlp_gemm(S1, S2, s_aW1, s_ab1, H, true, tid);  __syncthreads();
        mlp_gemm(H, nullptr, s_aW2, s_ab2, S1, false, tid); __syncthreads();
        // n7 = NOT(I7): S1 -> H -> S1
        mlp_gemm(S1, nullptr, s_nW1, s_nb1, H, true, tid);  __syncthreads();
        mlp_gemm(H,  nullptr, s_nW2, s_nb2, S1, false, tid); __syncthreads();

        // phase 2 gathers: e4->S2, pos->S0, neg->S3
        gather_row(embed, seq[grow * SEQLEN + 4], S2 + gr * XS, gq);
        gather_row(embed, pos_t[grow],            S0 + gr * XS, gq);
        gather_row(embed, neg_t[grow],            S3 + gr * XS, gq);
        __syncthreads();

        // I8 = OR(n7, e4): (S1,S2) -> H -> S1
        mlp_gemm(S1, S2, s_oW1, s_ob1, H, true, tid);  __syncthreads();
        mlp_gemm(H, nullptr, s_oW2, s_ob2, S1, false, tid); __syncthreads();
        // enc_not = NOT(I8): S1 -> H -> S1
        mlp_gemm(S1, nullptr, s_nW1, s_nb1, H, true, tid);  __syncthreads();
        mlp_gemm(H,  nullptr, s_nW2, s_nb2, S1, false, tid); __syncthreads();
        // encoded_pos = OR(enc_not, pos_e): (S1,S0) -> H -> S2
        mlp_gemm(S1, S0, s_oW1, s_ob1, H, true, tid);  __syncthreads();
        mlp_gemm(H, nullptr, s_oW2, s_ob2, S2, false, tid); __syncthreads();
        reduce_rows(S2, s_tv, tvnorm, out, tile * TILE, tid);
        // encoded_neg = OR(enc_not, neg_e): (S1,S3) -> H -> S2
        // (reduce above reads S2; first GEMM below writes only H, and the
        //  barrier after it orders the reduce before G2 overwrites S2)
        mlp_gemm(S1, S3, s_oW1, s_ob1, H, true, tid);  __syncthreads();
        mlp_gemm(H, nullptr, s_oW2, s_ob2, S2, false, tid); __syncthreads();
        reduce_rows(S2, s_tv, tvnorm, out, BATCHSZ + tile * TILE, tid);
        __syncthreads();   // protect S0..S3 before next tile's gathers
    }
}

extern "C" void kernel_launch(void* const* d_in, const int* in_sizes, int n_in,
                              void* d_out, int out_size)
{
    const int*   seq   = (const int*)d_in[0];
    const int*   pos_t = (const int*)d_in[1];
    const int*   neg_t = (const int*)d_in[2];
    const float* embed = (const float*)d_in[3];
    const float* tv    = (const float*)d_in[4];
    const float* nW1   = (const float*)d_in[5];
    const float* nb1   = (const float*)d_in[6];
    const float* nW2   = (const float*)d_in[7];
    const float* nb2   = (const float*)d_in[8];
    const float* aW1   = (const float*)d_in[9];
    const float* ab1   = (const float*)d_in[10];
    const float* aW2   = (const float*)d_in[11];
    const float* ab2   = (const float*)d_in[12];
    const float* oW1   = (const float*)d_in[13];
    const float* ob1   = (const float*)d_in[14];
    const float* oW2   = (const float*)d_in[15];
    const float* ob2   = (const float*)d_in[16];
    float* out = (float*)d_out;

    cudaFuncSetAttribute(logicnet_kernel,
                         cudaFuncAttributeMaxDynamicSharedMemorySize, SMEM_BYTES);

    int dev = 0, sm = 148;
    cudaGetDevice(&dev);
    cudaDeviceGetAttribute(&sm, cudaDevAttrMultiProcessorCount, dev);
    if (sm <= 0 || sm > NTILES) sm = 148;

    logicnet_kernel<<<sm, THREADS, SMEM_BYTES>>>(
        seq, pos_t, neg_t, embed, tv,
        nW1, nb1, nW2, nb2,
        aW1, ab1, aW2, ab2,
        oW1, ob1, oW2, ob2,
        out);
}

// round 8
// speedup vs baseline: 1.0443x; 1.0443x over previous
#include <cuda_runtime.h>
#include <cstdint>
#include <math.h>

#define EMBED    64
#define BATCHSZ  131072
#define SEQLEN   5
#define TILE     64
#define NTILES   (BATCHSZ / TILE)
#define THREADS  256
#define XS       68   // slot row stride in floats

typedef unsigned long long ull;

// ---------------- smem layout (float offsets) ----------------
#define O_NW1 0
#define O_NB1 4096
#define O_NW2 4160
#define O_NB2 8256
#define O_AW1 8320
#define O_AB1 16512
#define O_AW2 16576
#define O_AB2 20672
#define O_OW1 20736
#define O_OB1 28928
#define O_OW2 28992
#define O_OB2 33088
#define O_TV  33152
#define O_S0  33216
#define O_S1  (O_S0 + 64*XS)
#define O_S2  (O_S1 + 64*XS)
#define O_S3  (O_S2 + 64*XS)
#define O_H   (O_S3 + 64*XS)
#define SMEM_FLOATS (O_H + 64*XS)
#define SMEM_BYTES  (SMEM_FLOATS * 4)   // 219904 B

// ---------------- asm helpers ----------------
__device__ __forceinline__ ull pack2(float x) {
    ull p; asm("mov.b64 %0, {%1, %1};" : "=l"(p) : "f"(x)); return p;
}
__device__ __forceinline__ void fma2(ull& d, ull a, ull b) {
    asm("fma.rn.f32x2 %0, %1, %2, %0;" : "+l"(d) : "l"(a), "l"(b));
}
__device__ __forceinline__ float2 unpack2(ull p) {
    float lo, hi; asm("mov.b64 {%0, %1}, %2;" : "=f"(lo), "=f"(hi) : "l"(p));
    return make_float2(lo, hi);
}
__device__ __forceinline__ float4 lds128(unsigned a) {
    float4 v;
    asm("ld.shared.v4.f32 {%0,%1,%2,%3}, [%4];"
        : "=f"(v.x), "=f"(v.y), "=f"(v.z), "=f"(v.w) : "r"(a));
    return v;
}
__device__ __forceinline__ void lds2u64(ull& a, ull& b, unsigned ad) {
    asm("ld.shared.v2.u64 {%0,%1}, [%2];" : "=l"(a), "=l"(b) : "r"(ad));
}
__device__ __forceinline__ void sts128(unsigned a, float x, float y, float z, float w) {
    asm volatile("st.shared.v4.f32 [%0], {%1,%2,%3,%4};"
                 :: "r"(a), "f"(x), "f"(y), "f"(z), "f"(w) : "memory");
}
__device__ __forceinline__ void cp16(unsigned dst, const void* src) {
    asm volatile("cp.async.cg.shared.global [%0], [%1], 16;"
                 :: "r"(dst), "l"(src) : "memory");
}
__device__ __forceinline__ void cpcommit() {
    asm volatile("cp.async.commit_group;" ::: "memory");
}
template<int N>
__device__ __forceinline__ void cpwait() {
    asm volatile("cp.async.wait_group %0;" :: "n"(N) : "memory");
}

// ---------------- per-warp GEMM ----------------
// Y[8 x 64] = act( [X1 | X2] @ W + b ).  All addresses are absolute shared-mem
// byte addresses; x1/x2/y already include the warp's 8-row window offset.
// x2 == 0 -> K = 64.  Lane = 2 rows x 8 cols.
__device__ __noinline__ void wgemm(unsigned x1, unsigned x2, unsigned w,
                                   unsigned b, unsigned y, int act)
{
    const int lane = threadIdx.x & 31;
    const int rg = lane >> 3;           // 0..3 row-pair group
    const int cg = lane & 7;            // 0..7 col group (8 cols)
    const unsigned rowb = (unsigned)(rg * 2 * XS * 4);
    const unsigned c0b  = (unsigned)(cg * 32);

    ull a0[4], a1[4];
    lds2u64(a0[0], a0[1], b + c0b);
    lds2u64(a0[2], a0[3], b + c0b + 16);
    a1[0] = a0[0]; a1[1] = a0[1]; a1[2] = a0[2]; a1[3] = a0[3];

    const int nh = (x2 != 0u) ? 2 : 1;
#pragma unroll 1
    for (int h = 0; h < nh; h++) {
        const unsigned xb = h ? x2 : x1;
        const unsigned wb = w + (unsigned)(h * 16384) + c0b;  // 64*64*4 per half
#pragma unroll 4
        for (int k4 = 0; k4 < 16; k4++) {
            float4 xa = lds128(xb + rowb + k4 * 16);
            float4 xc = lds128(xb + rowb + XS * 4 + k4 * 16);
            float fa[4] = {xa.x, xa.y, xa.z, xa.w};
            float fc[4] = {xc.x, xc.y, xc.z, xc.w};
#pragma unroll
            for (int kk = 0; kk < 4; kk++) {
                ull w0, w1, w2, w3;
                unsigned wa = wb + (unsigned)((k4 * 4 + kk) * 256);
                lds2u64(w0, w1, wa);
                lds2u64(w2, w3, wa + 16);
                ull xp = pack2(fa[kk]);
                ull yp = pack2(fc[kk]);
                fma2(a0[0], xp, w0); fma2(a0[1], xp, w1);
                fma2(a0[2], xp, w2); fma2(a0[3], xp, w3);
                fma2(a1[0], yp, w0); fma2(a1[1], yp, w1);
                fma2(a1[2], yp, w2); fma2(a1[3], yp, w3);
            }
        }
    }

#pragma unroll
    for (int rr = 0; rr < 2; rr++) {
        ull* a = rr ? a1 : a0;
        float o[8];
#pragma unroll
        for (int j = 0; j < 4; j++) {
            float2 v = unpack2(a[j]);
            o[2 * j] = v.x; o[2 * j + 1] = v.y;
        }
        if (act) {
#pragma unroll
            for (int j = 0; j < 8; j++) o[j] = fmaxf(o[j], 0.01f * o[j]);
        }
        unsigned ya = y + rowb + (unsigned)(rr * XS * 4) + c0b;
        sts128(ya,      o[0], o[1], o[2], o[3]);
        sts128(ya + 16, o[4], o[5], o[6], o[7]);
    }
}

// Async gather of one 8-row embedding block into a warp-local slot window.
// Lane l copies row (l>>2), 16B chunks (l&3)+{0,4,8,12}.
__device__ __forceinline__ void cp_embed(unsigned slot_warp,
                                         const float* __restrict__ embed,
                                         int item, int lane)
{
    unsigned dst = slot_warp + (unsigned)((lane >> 2) * (XS * 4));
    const char* src = (const char*)(embed + (size_t)item * EMBED);
    int c = (lane & 3) * 16;
#pragma unroll
    for (int j = 0; j < 4; j++)
        cp16(dst + c + j * 64, src + c + j * 64);
}

// cosine*10 over the warp's 8 rows; 4 lanes per row.
__device__ __forceinline__ void wreduce(const float* __restrict__ Y,
                                        const float* __restrict__ tv,
                                        float tvnorm, float* __restrict__ out,
                                        int obase, int lane)
{
    const int rr = lane >> 2, q = lane & 3;
    const float4* er = (const float4*)(Y + rr * XS + q * 16);
    const float4* tr = (const float4*)(tv + q * 16);
    float num = 0.f, ss = 0.f;
#pragma unroll
    for (int j = 0; j < 4; j++) {
        float4 e = er[j], t = tr[j];
        num += e.x * t.x + e.y * t.y + e.z * t.z + e.w * t.w;
        ss  += e.x * e.x + e.y * e.y + e.z * e.z + e.w * e.w;
    }
    num += __shfl_xor_sync(0xffffffffu, num, 1);
    ss  += __shfl_xor_sync(0xffffffffu, ss, 1);
    num += __shfl_xor_sync(0xffffffffu, num, 2);
    ss  += __shfl_xor_sync(0xffffffffu, ss, 2);
    if (q == 0) {
        float denom = fmaxf(sqrtf(ss), 1e-8f) * tvnorm;
        out[obase + rr] = num / denom * 10.0f;
    }
}

__device__ __forceinline__ void copy_w(float* __restrict__ dst,
                                       const float* __restrict__ src, int n, int tid)
{
    for (int i = tid * 4; i < n; i += THREADS * 4)
        *(float4*)(dst + i) = *(const float4*)(src + i);
}

__global__ __launch_bounds__(THREADS, 1)
void logicnet_kernel(const int* __restrict__ seq,
                     const int* __restrict__ pos_t,
                     const int* __restrict__ neg_t,
                     const float* __restrict__ embed,
                     const float* __restrict__ true_vec,
                     const float* __restrict__ nW1, const float* __restrict__ nb1,
                     const float* __restrict__ nW2, const float* __restrict__ nb2,
                     const float* __restrict__ aW1, const float* __restrict__ ab1,
                     const float* __restrict__ aW2, const float* __restrict__ ab2,
                     const float* __restrict__ oW1, const float* __restrict__ ob1,
                     const float* __restrict__ oW2, const float* __restrict__ ob2,
                     float* __restrict__ out)
{
    extern __shared__ float smem[];
    const int tid = threadIdx.x;
    const int lane = tid & 31;
    const int wid = tid >> 5;

    // ---- weights + true_vec to smem, once ----
    copy_w(smem + O_NW1, nW1, 4096, tid);
    copy_w(smem + O_NB1, nb1,   64, tid);
    copy_w(smem + O_NW2, nW2, 4096, tid);
    copy_w(smem + O_NB2, nb2,   64, tid);
    copy_w(smem + O_AW1, aW1, 8192, tid);
    copy_w(smem + O_AB1, ab1,   64, tid);
    copy_w(smem + O_AW2, aW2, 4096, tid);
    copy_w(smem + O_AB2, ab2,   64, tid);
    copy_w(smem + O_OW1, oW1, 8192, tid);
    copy_w(smem + O_OB1, ob1,   64, tid);
    copy_w(smem + O_OW2, oW2, 4096, tid);
    copy_w(smem + O_OB2, ob2,   64, tid);
    copy_w(smem + O_TV,  true_vec, 64, tid);
    __syncthreads();   // the ONLY CTA barrier

    const unsigned sbase = (unsigned)__cvta_generic_to_shared(smem);
    const unsigned NW1a = sbase + O_NW1 * 4, NB1a = sbase + O_NB1 * 4;
    const unsigned NW2a = sbase + O_NW2 * 4, NB2a = sbase + O_NB2 * 4;
    const unsigned AW1a = sbase + O_AW1 * 4, AB1a = sbase + O_AB1 * 4;
    const unsigned AW2a = sbase + O_AW2 * 4, AB2a = sbase + O_AB2 * 4;
    const unsigned OW1a = sbase + O_OW1 * 4, OB1a = sbase + O_OB1 * 4;
    const unsigned OW2a = sbase + O_OW2 * 4, OB2a = sbase + O_OB2 * 4;

    const unsigned wwin = (unsigned)(wid * 8 * XS * 4);
    unsigned aS1 = sbase + O_S1 * 4 + wwin;
    unsigned aS2 = sbase + O_S2 * 4 + wwin;
    unsigned aH  = sbase + O_H  * 4 + wwin;
    unsigned aSA = sbase + O_S0 * 4 + wwin;   // parity-swapped slots
    unsigned aSB = sbase + O_S3 * 4 + wwin;

    const float* s_tv = smem + O_TV;
    float* gS1 = smem + O_S1 + wid * 8 * XS;
    float* gSA = smem + O_S0 + wid * 8 * XS;
    float* gSB = smem + O_S3 + wid * 8 * XS;

    float tvss = 0.f;
#pragma unroll
    for (int c = 0; c < 64; c++) tvss += s_tv[c] * s_tv[c];
    const float tvnorm = fmaxf(sqrtf(tvss), 1e-8f);

    int t = blockIdx.x;
    const int stride = gridDim.x;

    // ---- prologue: prefetch e1,e0,e2,e3 for first tile ----
    {
        int r = t * TILE + wid * 8 + (lane >> 2);
        const int* sq = seq + (size_t)r * SEQLEN;
        cp_embed(aSA, embed, sq[1], lane); cpcommit();
        cp_embed(aS1, embed, sq[0], lane); cpcommit();
        cp_embed(aS2, embed, sq[2], lane); cpcommit();
        cp_embed(aSB, embed, sq[3], lane); cpcommit();
    }

#pragma unroll 1
    for (; t < NTILES; t += stride) {
        const int r = t * TILE + wid * 8 + (lane >> 2);
        const int ipos = pos_t[r];
        const int ineg = neg_t[r];
        const int ie4  = seq[(size_t)r * SEQLEN + 4];
        const int tn = t + stride;
        const bool hn = (tn < NTILES);
        int i1n = 0, i0n = 0, i2n = 0, i3n = 0;
        if (hn) {
            const int rn = tn * TILE + wid * 8 + (lane >> 2);
            const int* sq = seq + (size_t)rn * SEQLEN;
            i1n = sq[1]; i0n = sq[0]; i2n = sq[2]; i3n = sq[3];
        }

        cpwait<3>(); __syncwarp();                       // e1 (SA) ready
        wgemm(aSA, 0, NW1a, NB1a, aH, 1);                // n1 L1
        wgemm(aH,  0, NW2a, NB2a, aSA, 0);               // n1 -> SA
        cpwait<2>(); __syncwarp();                       // e0 (S1) ready
        wgemm(aS1, aSA, AW1a, AB1a, aH, 1);              // AND(e0,n1) L1
        cp_embed(aS1, embed, ipos, lane); cpcommit();    // pos -> S1
        wgemm(aH,  0, AW2a, AB2a, aSA, 0);               // I5 -> SA
        cpwait<1>(); __syncwarp();                       // e2,e3 ready
        wgemm(aS2, aSB, OW1a, OB1a, aH, 1);              // OR(e2,e3) L1
        cp_embed(aSB, embed, ie4, lane); cpcommit();     // e4 -> SB
        wgemm(aH,  0, OW2a, OB2a, aS2, 0);               // I6 -> S2
        wgemm(aSA, aS2, AW1a, AB1a, aH, 1);              // AND(I5,I6) L1
        cp_embed(aSA, embed, ineg, lane); cpcommit();    // neg -> SA
        wgemm(aH,  0, AW2a, AB2a, aS2, 0);               // I7 -> S2
        wgemm(aS2, 0, NW1a, NB1a, aH, 1);                // n7 L1
        wgemm(aH,  0, NW2a, NB2a, aS2, 0);               // n7 -> S2
        cpwait<1>(); __syncwarp();                       // e4 (SB), pos ready
        wgemm(aS2, aSB, OW1a, OB1a, aH, 1);              // OR(n7,e4) L1
        if (hn) cp_embed(aSB, embed, i1n, lane);
        cpcommit();                                      // e1' -> SB
        wgemm(aH,  0, OW2a, OB2a, aS2, 0);               // I8 -> S2
        wgemm(aS2, 0, NW1a, NB1a, aH, 1);                // enc_not L1
        wgemm(aH,  0, NW2a, NB2a, aS2, 0);               // enc_not -> S2
        wgemm(aS2, aS1, OW1a, OB1a, aH, 1);              // OR(enc_not,pos) L1
        wgemm(aH,  0, OW2a, OB2a, aS1, 0);               // enc_pos -> S1
        wreduce(gS1, s_tv, tvnorm, out, t * TILE + wid * 8, lane);
        if (hn) cp_embed(aS1, embed, i0n, lane);
        cpcommit();                                      // e0' -> S1
        cpwait<2>(); __syncwarp();                       // neg (SA) ready
        wgemm(aS2, aSA, OW1a, OB1a, aH, 1);              // OR(enc_not,neg) L1
        if (hn) cp_embed(aS2, embed, i2n, lane);
        cpcommit();                                      // e2' -> S2
        wgemm(aH,  0, OW2a, OB2a, aSA, 0);               // enc_neg -> SA
        wreduce(gSA, s_tv, tvnorm, out, BATCHSZ + t * TILE + wid * 8, lane);
        if (hn) cp_embed(aSA, embed, i3n, lane);
        cpcommit();                                      // e3' -> SA

        unsigned tu = aSA; aSA = aSB; aSB = tu;
        float* tg = gSA; gSA = gSB; gSB = tg;
    }
}

extern "C" void kernel_launch(void* const* d_in, const int* in_sizes, int n_in,
                              void* d_out, int out_size)
{
    const int*   seq   = (const int*)d_in[0];
    const int*   pos_t = (const int*)d_in[1];
    const int*   neg_t = (const int*)d_in[2];
    const float* embed = (const float*)d_in[3];
    const float* tv    = (const float*)d_in[4];
    const float* nW1   = (const float*)d_in[5];
    const float* nb1   = (const float*)d_in[6];
    const float* nW2   = (const float*)d_in[7];
    const float* nb2   = (const float*)d_in[8];
    const float* aW1   = (const float*)d_in[9];
    const float* ab1   = (const float*)d_in[10];
    const float* aW2   = (const float*)d_in[11];
    const float* ab2   = (const float*)d_in[12];
    const float* oW1   = (const float*)d_in[13];
    const float* ob1   = (const float*)d_in[14];
    const float* oW2   = (const float*)d_in[15];
    const float* ob2   = (const float*)d_in[16];
    float* out = (float*)d_out;

    cudaFuncSetAttribute(logicnet_kernel,
                         cudaFuncAttributeMaxDynamicSharedMemorySize, SMEM_BYTES);

    int dev = 0, sm = 148;
    cudaGetDevice(&dev);
    cudaDeviceGetAttribute(&sm, cudaDevAttrMultiProcessorCount, dev);
    if (sm <= 0 || sm > NTILES) sm = 148;

    logicnet_kernel<<<sm, THREADS, SMEM_BYTES>>>(
        seq, pos_t, neg_t, embed, tv,
        nW1, nb1, nW2, nb2,
        aW1, ab1, aW2, ab2,
        oW1, ob1, oW2, ob2,
        out);
}

// round 10
// speedup vs baseline: 1.7171x; 1.6443x over previous
#include <cuda_runtime.h>
#include <cstdint>
#include <math.h>

#define EMBED    64
#define BATCHSZ  131072
#define SEQLEN   5
#define TILE     64
#define NTILES   (BATCHSZ / TILE)
#define THREADS  128

typedef unsigned long long ull;

// ---------------- smem layout (float offsets) ----------------
// Blocked-transposed weights: WT[k4][c][j] = W[4*k4+j][c], 256 floats/block.
#define O_NT1 0        /* NOT W1  64x64  -> 16 blocks */
#define O_NT2 4096     /* NOT W2  64x64  */
#define O_AT1 8192     /* AND W1 128x64  -> 32 blocks */
#define O_AT2 16384    /* AND W2  64x64  */
#define O_OT1 20480    /* OR  W1 128x64  */
#define O_OT2 28672    /* OR  W2  64x64  */
#define O_NB1 32768
#define O_NB2 32832
#define O_AB1 32896
#define O_AB2 32960
#define O_OB1 33024
#define O_OB2 33088
#define O_TV  33152
// activation slots: 64 rows x 64 floats (row stride 256 B)
#define O_S0  33216
#define O_S1  (O_S0 + 4096)
#define O_S2  (O_S1 + 4096)
#define O_S3  (O_S2 + 4096)
#define O_H   (O_S3 + 4096)
#define SMEM_FLOATS (O_H + 4096)
#define SMEM_BYTES  (SMEM_FLOATS * 4)   // 214784 B

// ---------------- asm helpers ----------------
__device__ __forceinline__ void fma2(ull& d, ull a, ull b) {
    asm("fma.rn.f32x2 %0, %1, %2, %0;" : "+l"(d) : "l"(a), "l"(b));
}
__device__ __forceinline__ float2 unpack2(ull p) {
    float lo, hi; asm("mov.b64 {%0, %1}, %2;" : "=f"(lo), "=f"(hi) : "l"(p));
    return make_float2(lo, hi);
}
__device__ __forceinline__ ull mkpair(float b) {   // (b, 0)
    ull p; asm("mov.b64 %0, {%1, %2};" : "=l"(p) : "f"(b), "f"(0.0f)); return p;
}
__device__ __forceinline__ void lds2u64(ull& a, ull& b, unsigned ad) {
    asm("ld.shared.v2.u64 {%0,%1}, [%2];" : "=l"(a), "=l"(b) : "r"(ad));
}
__device__ __forceinline__ float ldsf(unsigned a) {
    float v; asm("ld.shared.f32 %0, [%1];" : "=f"(v) : "r"(a));
    return v;
}
__device__ __forceinline__ void stsf(unsigned a, float v) {
    asm volatile("st.shared.f32 [%0], %1;" :: "r"(a), "f"(v) : "memory");
}
__device__ __forceinline__ void cp16(unsigned dst, const void* src) {
    asm volatile("cp.async.cg.shared.global [%0], [%1], 16;"
                 :: "r"(dst), "l"(src) : "memory");
}
__device__ __forceinline__ void cpcommit() {
    asm volatile("cp.async.commit_group;" ::: "memory");
}
template<int N>
__device__ __forceinline__ void cpwait() {
    asm volatile("cp.async.wait_group %0;" :: "n"(N) : "memory");
}

// ---------------- per-warp GEMM, K-packed, blocked W ----------------
// Y[16 x 64] = act( [X1 | X2] @ W + b ).  wt = blocked WT base; x1/x2/y =
// warp's 16-row windows (row stride 256 B).  x2 == 0 -> K = 64.
// Lane owns cols (lane, lane+32); acc f32x2 = (even-k sum, odd-k sum).
__device__ __noinline__ void wgemm(unsigned x1, unsigned x2, unsigned wt,
                                   unsigned bia, unsigned y, int act)
{
    const int lane = threadIdx.x & 31;
    const unsigned cA = (unsigned)(lane * 4);      // col lane
    const unsigned cB = cA + 128u;                 // col lane+32

    ull acc0[16], acc1[16];
    const ull bp0 = mkpair(ldsf(bia + cA));
    const ull bp1 = mkpair(ldsf(bia + cB));
#pragma unroll
    for (int r = 0; r < 16; r++) { acc0[r] = bp0; acc1[r] = bp1; }

    const unsigned wlane = (unsigned)(lane * 16);
    const int nh = (x2 != 0u) ? 2 : 1;

#pragma unroll 1
    for (int h = 0; h < nh; h++) {
        const unsigned xb = h ? x2 : x1;
        const unsigned wb = wt + (unsigned)(h * 16384) + wlane;  // 16 blocks/half
#pragma unroll 1
        for (int k4 = 0; k4 < 16; k4++) {
            ull wA0, wA1, wB0, wB1;
            // block k4: cols 0..31 at +0, cols 32..63 at +512; lane-coalesced
            lds2u64(wA0, wA1, wb + (unsigned)(k4 * 1024));
            lds2u64(wB0, wB1, wb + (unsigned)(k4 * 1024) + 512u);
#pragma unroll
            for (int r = 0; r < 16; r++) {
                ull x01, x23;                      // warp-uniform: broadcast
                lds2u64(x01, x23, xb + (unsigned)(r * 256 + k4 * 16));
                fma2(acc0[r], x01, wA0);
                fma2(acc0[r], x23, wA1);
                fma2(acc1[r], x01, wB0);
                fma2(acc1[r], x23, wB1);
            }
        }
    }

#pragma unroll
    for (int r = 0; r < 16; r++) {
        float2 a = unpack2(acc0[r]);
        float2 b = unpack2(acc1[r]);
        float y0 = a.x + a.y;
        float y1 = b.x + b.y;
        if (act) {
            y0 = fmaxf(y0, 0.01f * y0);
            y1 = fmaxf(y1, 0.01f * y1);
        }
        const unsigned yr = y + (unsigned)(r * 256);
        stsf(yr + cA, y0);
        stsf(yr + cB, y1);
    }
}

// Async gather: 16-row embedding block into warp slot window.
// 2 lanes per row; each lane copies 128 B of the 256-B row.
__device__ __forceinline__ void cp_embed(unsigned slot_warp,
                                         const float* __restrict__ embed,
                                         int item, int lane)
{
    const unsigned half = (unsigned)(lane & 1) * 128u;
    const unsigned dst = slot_warp + (unsigned)((lane >> 1) * 256) + half;
    const char* src = (const char*)(embed + (size_t)item * EMBED) + half;
#pragma unroll
    for (int j = 0; j < 8; j++)
        cp16(dst + j * 16, src + j * 16);
}

// cosine*10 over the warp's 16 rows; 2 lanes per row.
__device__ __forceinline__ void wreduce(const float* __restrict__ Y,
                                        const float* __restrict__ tv,
                                        float tvnorm, float* __restrict__ out,
                                        int obase, int lane)
{
    const int rr = lane >> 1, q = lane & 1;
    const float4* er = (const float4*)(Y + rr * 64 + q * 32);
    const float4* tr = (const float4*)(tv + q * 32);
    float num = 0.f, ss = 0.f;
#pragma unroll
    for (int j = 0; j < 8; j++) {
        float4 e = er[j], t = tr[j];
        num += e.x * t.x + e.y * t.y + e.z * t.z + e.w * t.w;
        ss  += e.x * e.x + e.y * e.y + e.z * e.z + e.w * e.w;
    }
    num += __shfl_xor_sync(0xffffffffu, num, 1);
    ss  += __shfl_xor_sync(0xffffffffu, ss, 1);
    if (q == 0) {
        float denom = fmaxf(sqrtf(ss), 1e-8f) * tvnorm;
        out[obase + rr] = num / denom * 10.0f;
    }
}

// One-time blocked transpose: dst[k4*256 + c*4 + j] = src[(4*k4+j)*64 + c]
template<int K>
__device__ void copy_wt(float* __restrict__ dst, const float* __restrict__ src, int tid)
{
#pragma unroll 1
    for (int i = tid; i < 64 * K; i += THREADS) {
        int blk = i >> 8;          // k4 block
        int rem = i & 255;
        int c = rem >> 2;
        int j = rem & 3;
        dst[i] = src[(blk * 4 + j) * 64 + c];
    }
}
__device__ __forceinline__ void copy_v(float* __restrict__ dst,
                                       const float* __restrict__ src, int n, int tid)
{
    for (int i = tid; i < n; i += THREADS) dst[i] = src[i];
}

__global__ __launch_bounds__(THREADS, 1)
void logicnet_kernel(const int* __restrict__ seq,
                     const int* __restrict__ pos_t,
                     const int* __restrict__ neg_t,
                     const float* __restrict__ embed,
                     const float* __restrict__ true_vec,
                     const float* __restrict__ nW1, const float* __restrict__ nb1,
                     const float* __restrict__ nW2, const float* __restrict__ nb2,
                     const float* __restrict__ aW1, const float* __restrict__ ab1,
                     const float* __restrict__ aW2, const float* __restrict__ ab2,
                     const float* __restrict__ oW1, const float* __restrict__ ob1,
                     const float* __restrict__ oW2, const float* __restrict__ ob2,
                     float* __restrict__ out)
{
    extern __shared__ float smem[];
    const int tid = threadIdx.x;
    const int lane = tid & 31;
    const int wid = tid >> 5;          // 0..3

    // ---- blocked-transpose weights + biases/tv into smem (once) ----
    copy_wt<64> (smem + O_NT1, nW1, tid);
    copy_wt<64> (smem + O_NT2, nW2, tid);
    copy_wt<128>(smem + O_AT1, aW1, tid);
    copy_wt<64> (smem + O_AT2, aW2, tid);
    copy_wt<128>(smem + O_OT1, oW1, tid);
    copy_wt<64> (smem + O_OT2, oW2, tid);
    copy_v(smem + O_NB1, nb1, 64, tid);
    copy_v(smem + O_NB2, nb2, 64, tid);
    copy_v(smem + O_AB1, ab1, 64, tid);
    copy_v(smem + O_AB2, ab2, 64, tid);
    copy_v(smem + O_OB1, ob1, 64, tid);
    copy_v(smem + O_OB2, ob2, 64, tid);
    copy_v(smem + O_TV,  true_vec, 64, tid);
    __syncthreads();   // the ONLY CTA barrier

    const unsigned sbase = (unsigned)__cvta_generic_to_shared(smem);
    const unsigned NT1 = sbase + O_NT1 * 4, NB1a = sbase + O_NB1 * 4;
    const unsigned NT2 = sbase + O_NT2 * 4, NB2a = sbase + O_NB2 * 4;
    const unsigned AT1 = sbase + O_AT1 * 4, AB1a = sbase + O_AB1 * 4;
    const unsigned AT2 = sbase + O_AT2 * 4, AB2a = sbase + O_AB2 * 4;
    const unsigned OT1 = sbase + O_OT1 * 4, OB1a = sbase + O_OB1 * 4;
    const unsigned OT2 = sbase + O_OT2 * 4, OB2a = sbase + O_OB2 * 4;

    const unsigned wwin = (unsigned)(wid * 16 * 256);   // 16 rows x 256 B
    unsigned aS1 = sbase + O_S1 * 4 + wwin;
    unsigned aS2 = sbase + O_S2 * 4 + wwin;
    unsigned aH  = sbase + O_H  * 4 + wwin;
    unsigned aSA = sbase + O_S0 * 4 + wwin;   // parity-swapped slots
    unsigned aSB = sbase + O_S3 * 4 + wwin;

    const float* s_tv = smem + O_TV;
    float* gS1 = smem + O_S1 + wid * 16 * 64;
    float* gSA = smem + O_S0 + wid * 16 * 64;
    float* gSB = smem + O_S3 + wid * 16 * 64;

    float tvss = 0.f;
#pragma unroll
    for (int c = 0; c < 64; c++) tvss += s_tv[c] * s_tv[c];
    const float tvnorm = fmaxf(sqrtf(tvss), 1e-8f);

    int t = blockIdx.x;
    const int stride = gridDim.x;

    // ---- prologue: prefetch e1,e0,e2,e3 for first tile ----
    {
        int r = t * TILE + wid * 16 + (lane >> 1);
        const int* sq = seq + (size_t)r * SEQLEN;
        cp_embed(aSA, embed, sq[1], lane); cpcommit();
        cp_embed(aS1, embed, sq[0], lane); cpcommit();
        cp_embed(aS2, embed, sq[2], lane); cpcommit();
        cp_embed(aSB, embed, sq[3], lane); cpcommit();
    }

#pragma unroll 1
    for (; t < NTILES; t += stride) {
        const int r = t * TILE + wid * 16 + (lane >> 1);
        const int ipos = pos_t[r];
        const int ineg = neg_t[r];
        const int ie4  = seq[(size_t)r * SEQLEN + 4];
        const int tn = t + stride;
        const bool hn = (tn < NTILES);
        int i1n = 0, i0n = 0, i2n = 0, i3n = 0;
        if (hn) {
            const int rn = tn * TILE + wid * 16 + (lane >> 1);
            const int* sq = seq + (size_t)rn * SEQLEN;
            i1n = sq[1]; i0n = sq[0]; i2n = sq[2]; i3n = sq[3];
        }

        cpwait<3>(); __syncwarp();                       // e1 (SA) ready
        wgemm(aSA, 0, NT1, NB1a, aH, 1);                 // n1 L1
        wgemm(aH,  0, NT2, NB2a, aSA, 0);                // n1 -> SA
        cpwait<2>(); __syncwarp();                       // e0 (S1) ready
        wgemm(aS1, aSA, AT1, AB1a, aH, 1);               // AND(e0,n1) L1
        cp_embed(aS1, embed, ipos, lane); cpcommit();    // pos -> S1
        wgemm(aH,  0, AT2, AB2a, aSA, 0);                // I5 -> SA
        cpwait<1>(); __syncwarp();                       // e2,e3 ready
        wgemm(aS2, aSB, OT1, OB1a, aH, 1);               // OR(e2,e3) L1
        cp_embed(aSB, embed, ie4, lane); cpcommit();     // e4 -> SB
        wgemm(aH,  0, OT2, OB2a, aS2, 0);                // I6 -> S2
        wgemm(aSA, aS2, AT1, AB1a, aH, 1);               // AND(I5,I6) L1
        cp_embed(aSA, embed, ineg, lane); cpcommit();    // neg -> SA
        wgemm(aH,  0, AT2, AB2a, aS2, 0);                // I7 -> S2
        wgemm(aS2, 0, NT1, NB1a, aH, 1);                 // n7 L1
        wgemm(aH,  0, NT2, NB2a, aS2, 0);                // n7 -> S2
        cpwait<1>(); __syncwarp();                       // e4 (SB), pos ready
        wgemm(aS2, aSB, OT1, OB1a, aH, 1);               // OR(n7,e4) L1
        if (hn) cp_embed(aSB, embed, i1n, lane);
        cpcommit();                                      // e1' -> SB
        wgemm(aH,  0, OT2, OB2a, aS2, 0);                // I8 -> S2
        wgemm(aS2, 0, NT1, NB1a, aH, 1);                 // enc_not L1
        wgemm(aH,  0, NT2, NB2a, aS2, 0);                // enc_not -> S2
        wgemm(aS2, aS1, OT1, OB1a, aH, 1);               // OR(enc_not,pos) L1
        wgemm(aH,  0, OT2, OB2a, aS1, 0);                // enc_pos -> S1
        wreduce(gS1, s_tv, tvnorm, out, t * TILE + wid * 16, lane);
        if (hn) cp_embed(aS1, embed, i0n, lane);
        cpcommit();                                      // e0' -> S1
        cpwait<2>(); __syncwarp();                       // neg (SA) ready
        wgemm(aS2, aSA, OT1, OB1a, aH, 1);               // OR(enc_not,neg) L1
        if (hn) cp_embed(aS2, embed, i2n, lane);
        cpcommit();                                      // e2' -> S2
        wgemm(aH,  0, OT2, OB2a, aSA, 0);                // enc_neg -> SA
        wreduce(gSA, s_tv, tvnorm, out, BATCHSZ + t * TILE + wid * 16, lane);
        if (hn) cp_embed(aSA, embed, i3n, lane);
        cpcommit();                                      // e3' -> SA

        unsigned tu = aSA; aSA = aSB; aSB = tu;
        float* tg = gSA; gSA = gSB; gSB = tg;
    }
}

extern "C" void kernel_launch(void* const* d_in, const int* in_sizes, int n_in,
                              void* d_out, int out_size)
{
    const int*   seq   = (const int*)d_in[0];
    const int*   pos_t = (const int*)d_in[1];
    const int*   neg_t = (const int*)d_in[2];
    const float* embed = (const float*)d_in[3];
    const float* tv    = (const float*)d_in[4];
    const float* nW1   = (const float*)d_in[5];
    const float* nb1   = (const float*)d_in[6];
    const float* nW2   = (const float*)d_in[7];
    const float* nb2   = (const float*)d_in[8];
    const float* aW1   = (const float*)d_in[9];
    const float* ab1   = (const float*)d_in[10];
    const float* aW2   = (const float*)d_in[11];
    const float* ab2   = (const float*)d_in[12];
    const float* oW1   = (const float*)d_in[13];
    const float* ob1   = (const float*)d_in[14];
    const float* oW2   = (const float*)d_in[15];
    const float* ob2   = (const float*)d_in[16];
    float* out = (float*)d_out;

    cudaFuncSetAttribute(logicnet_kernel,
                         cudaFuncAttributeMaxDynamicSharedMemorySize, SMEM_BYTES);

    int dev = 0, sm = 148;
    cudaGetDevice(&dev);
    cudaDeviceGetAttribute(&sm, cudaDevAttrMultiProcessorCount, dev);
    if (sm <= 0 || sm > NTILES) sm = 148;

    logicnet_kernel<<<sm, THREADS, SMEM_BYTES>>>(
        seq, pos_t, neg_t, embed, tv,
        nW1, nb1, nW2, nb2,
        aW1, ab1, aW2, ab2,
        oW1, ob1, oW2, ob2,
        out);
}